// round 9
// baseline (speedup 1.0000x reference)
#include <cuda_runtime.h>
#include <cuda_bf16.h>

// AMSoftmaxLoss: score (2048 x 50257) fp32, labels (2048) int32 in {0,1}
// Persistent 1184 blocks; block-level prefetched ticket over 16384
// eighth-row tiles (~25KB, ~5us). One __syncthreads per tile; per-warp
// partials (tile lives in one row) -> no block reduction.
// Last-arriving block folds 64 partials/row + epilogue.

#define NROWS 2048
#define CCOLS 50257
#define NBLK  1184            // 148 SMs * 8 resident blocks
#define BLK   256
#define NW    (BLK / 32)      // 8 warps
#define SEGS  8
#define SEGW  6283            // 7*6283 + 6276 = 50257
#define NTILES (NROWS * SEGS) // 16384

__device__ float g_part[NTILES * NW];  // 512 KB
__device__ int g_ticket = 0;           // reset by finalize block each launch
__device__ unsigned int g_count = 0;   // self-resetting via atomicInc wrap

__device__ __forceinline__ float ex2f(float x) {
    float y;
    asm("ex2.approx.ftz.f32 %0, %1;" : "=f"(y) : "f"(x));
    return y;
}

#define SL2E (30.0f * 1.44269504088896340736f)   // S * log2(e)

__global__ __launch_bounds__(BLK) void amsm_kernel(
    const float* __restrict__ score,
    const int* __restrict__ labels,
    float* __restrict__ out)
{
    const int tid  = threadIdx.x;
    const int lane = tid & 31;
    const int wid  = tid >> 5;

    __shared__ int s_tile[2];

    if (tid == 0) s_tile[0] = atomicAdd(&g_ticket, 1);
    __syncthreads();
    int buf = 0;
    int t = s_tile[0];

    while (t < NTILES) {
        int tn = 0;
        if (tid == 0) tn = atomicAdd(&g_ticket, 1);    // prefetch next ticket

        const int r    = t >> 3;
        const int seg  = t & 7;
        const int col0 = seg * SEGW;
        const int len  = (seg == SEGS - 1) ? (CCOLS - col0) : SEGW;
        const float* __restrict__ p = score + (size_t)r * CCOLS + col0;

        float s0 = 0.f, s1 = 0.f, s2 = 0.f, s3 = 0.f;

        int peel = (-(r * CCOLS + col0)) & 3;          // to 16B alignment
        if (tid < peel) s0 += ex2f(SL2E * p[tid]);

        const int n4 = (len - peel) >> 2;
        const float4* __restrict__ q = (const float4*)(p + peel);

        int i = tid;
        for (; i + 3 * BLK < n4; i += 4 * BLK) {       // 4 LDG.128 in flight
            float4 a = __ldcs(q + i);
            float4 b = __ldcs(q + i + BLK);
            float4 c = __ldcs(q + i + 2 * BLK);
            float4 d = __ldcs(q + i + 3 * BLK);
            s0 += ex2f(SL2E * a.x); s1 += ex2f(SL2E * a.y);
            s2 += ex2f(SL2E * a.z); s3 += ex2f(SL2E * a.w);
            s0 += ex2f(SL2E * b.x); s1 += ex2f(SL2E * b.y);
            s2 += ex2f(SL2E * b.z); s3 += ex2f(SL2E * b.w);
            s0 += ex2f(SL2E * c.x); s1 += ex2f(SL2E * c.y);
            s2 += ex2f(SL2E * c.z); s3 += ex2f(SL2E * c.w);
            s0 += ex2f(SL2E * d.x); s1 += ex2f(SL2E * d.y);
            s2 += ex2f(SL2E * d.z); s3 += ex2f(SL2E * d.w);
        }
        for (; i < n4; i += BLK) {
            float4 a = __ldcs(q + i);
            s0 += ex2f(SL2E * a.x); s1 += ex2f(SL2E * a.y);
            s2 += ex2f(SL2E * a.z); s3 += ex2f(SL2E * a.w);
        }
        const int done = peel + 4 * n4;
        if (tid < len - done) s0 += ex2f(SL2E * p[done + tid]);

        float v = (s0 + s1) + (s2 + s3);
        #pragma unroll
        for (int off = 16; off > 0; off >>= 1)
            v += __shfl_down_sync(0xFFFFFFFFu, v, off);
        if (lane == 0) g_part[t * NW + wid] = v;       // per-warp partial

        if (tid == 0) s_tile[buf ^ 1] = tn;
        __syncthreads();                               // one barrier per tile
        buf ^= 1;
        t = s_tile[buf];
    }

    // ---- completion; last-arriving block finalizes ----
    __syncthreads();
    __shared__ unsigned s_last;
    if (tid == 0) {
        __threadfence();
        unsigned old = atomicInc(&g_count, NBLK - 1);  // wraps -> self-reset
        s_last = (old == NBLK - 1) ? 1u : 0u;
    }
    __syncthreads();
    if (!s_last) return;

    if (tid == 0) g_ticket = 0;            // clean for next graph replay

    volatile float* gp = g_part;
    double acc = 0.0;
    for (int r = tid; r < NROWS; r += BLK) {
        float rs = 0.f;
        #pragma unroll 8
        for (int k = 0; k < SEGS * NW; k++)
            rs += gp[r * SEGS * NW + k];

        int lab = labels[r] & 1;
        float m = lab ? 0.4f : 0.1f;
        float tg = __ldg(score + (size_t)r * CCOLS + lab);
        float num = 30.0f * (tg - m);
        float excl = rs - ex2f(SL2E * tg);
        float denom = ex2f(num * 1.44269504088896340736f) + excl;
        acc += (double)(num - logf(denom));
    }

    __shared__ double dred[BLK];
    dred[tid] = acc;
    __syncthreads();
    #pragma unroll
    for (int off = BLK / 2; off > 0; off >>= 1) {
        if (tid < off) dred[tid] += dred[tid + off];
        __syncthreads();
    }
    if (tid == 0)
        out[0] = (float)(-dred[0] / (double)NROWS);
}

extern "C" void kernel_launch(void* const* d_in, const int* in_sizes, int n_in,
                              void* d_out, int out_size)
{
    const float* score = (const float*)d_in[0];
    const int* labels = (const int*)d_in[1];
    float* out = (float*)d_out;

    amsm_kernel<<<NBLK, BLK>>>(score, labels, out);
}

// round 10
// speedup vs baseline: 1.7054x; 1.7054x over previous
#include <cuda_runtime.h>
#include <cuda_bf16.h>

// AMSoftmaxLoss: score (2048 x 50257) fp32, labels (2048) int32 in {0,1}
// 4096 half-row blocks (plain LDG.128, no .cs), HW-scheduled backfill.
// Last-arriving block folds 2 partials/row + epilogue (fused finale).

#define NROWS 2048
#define CCOLS 50257
#define BLK   256
#define SEGS  2
#define SEGW  25129            // seg0 = 25129, seg1 = 25128
#define NTILES (NROWS * SEGS)  // 4096

__device__ float g_part[NTILES];
__device__ unsigned int g_count = 0;   // self-resetting via atomicInc wrap

__device__ __forceinline__ float ex2f(float x) {
    float y;
    asm("ex2.approx.ftz.f32 %0, %1;" : "=f"(y) : "f"(x));
    return y;
}

#define SL2E (30.0f * 1.44269504088896340736f)   // S * log2(e)

__global__ __launch_bounds__(BLK) void amsm_kernel(
    const float* __restrict__ score,
    const int* __restrict__ labels,
    float* __restrict__ out)
{
    const int t    = blockIdx.x;
    const int tid  = threadIdx.x;
    const int lane = tid & 31;
    const int wid  = tid >> 5;

    const int r    = t >> 1;
    const int seg  = t & 1;
    const int col0 = seg * SEGW;
    const int len  = seg ? (CCOLS - SEGW) : SEGW;
    const float* __restrict__ p = score + (size_t)r * CCOLS + col0;

    float s0 = 0.f, s1 = 0.f, s2 = 0.f, s3 = 0.f;

    int peel = (-(r * CCOLS + col0)) & 3;          // to 16B alignment
    if (tid < peel) s0 += ex2f(SL2E * p[tid]);

    const int n4 = (len - peel) >> 2;
    const float4* __restrict__ q = (const float4*)(p + peel);

    int i = tid;
    for (; i + BLK < n4; i += 2 * BLK) {           // 2 LDG.128 in flight
        float4 a = q[i];
        float4 b = q[i + BLK];
        s0 += ex2f(SL2E * a.x); s1 += ex2f(SL2E * a.y);
        s2 += ex2f(SL2E * a.z); s3 += ex2f(SL2E * a.w);
        s0 += ex2f(SL2E * b.x); s1 += ex2f(SL2E * b.y);
        s2 += ex2f(SL2E * b.z); s3 += ex2f(SL2E * b.w);
    }
    for (; i < n4; i += BLK) {
        float4 a = q[i];
        s0 += ex2f(SL2E * a.x); s1 += ex2f(SL2E * a.y);
        s2 += ex2f(SL2E * a.z); s3 += ex2f(SL2E * a.w);
    }
    const int done = peel + 4 * n4;
    if (tid < len - done) s0 += ex2f(SL2E * p[done + tid]);

    float v = (s0 + s1) + (s2 + s3);

    // Block reduction: warp shuffle then cross-warp via smem.
    __shared__ float wsum[BLK / 32];
    #pragma unroll
    for (int off = 16; off > 0; off >>= 1)
        v += __shfl_down_sync(0xFFFFFFFFu, v, off);
    if (lane == 0) wsum[wid] = v;
    __syncthreads();

    __shared__ unsigned s_last;
    if (tid == 0) {
        float w = 0.f;
        #pragma unroll
        for (int k = 0; k < BLK / 32; k++) w += wsum[k];
        g_part[t] = w;
        __threadfence();
        unsigned old = atomicInc(&g_count, NTILES - 1);  // wraps -> self-reset
        s_last = (old == NTILES - 1) ? 1u : 0u;
    }
    __syncthreads();
    if (!s_last) return;

    // ---- Last-arriving block: fold partials, per-row epilogue, mean ----
    volatile float* gp = g_part;
    double acc = 0.0;
    for (int r2 = tid; r2 < NROWS; r2 += BLK) {
        float rs = gp[2 * r2] + gp[2 * r2 + 1];

        int lab = labels[r2] & 1;
        float m = lab ? 0.4f : 0.1f;
        float tg = __ldg(score + (size_t)r2 * CCOLS + lab);
        float num = 30.0f * (tg - m);
        float excl = rs - ex2f(SL2E * tg);
        float denom = ex2f(num * 1.44269504088896340736f) + excl;
        acc += (double)(num - logf(denom));
    }

    __shared__ double dred[BLK];
    dred[tid] = acc;
    __syncthreads();
    #pragma unroll
    for (int off = BLK / 2; off > 0; off >>= 1) {
        if (tid < off) dred[tid] += dred[tid + off];
        __syncthreads();
    }
    if (tid == 0)
        out[0] = (float)(-dred[0] / (double)NROWS);
}

extern "C" void kernel_launch(void* const* d_in, const int* in_sizes, int n_in,
                              void* d_out, int out_size)
{
    const float* score = (const float*)d_in[0];
    const int* labels = (const int*)d_in[1];
    float* out = (float*)d_out;

    amsm_kernel<<<NTILES, BLK>>>(score, labels, out);
}

// round 11
// speedup vs baseline: 1.8732x; 1.0984x over previous
#include <cuda_runtime.h>
#include <cuda_bf16.h>

// AMSoftmaxLoss: score (2048 x 50257) fp32, labels (2048) int32 in {0,1}
// R3 champion structure (one block per row, plain LDG.128, fused finale),
// inner loop deepened to 4 float4 in flight per thread.

#define NROWS 2048
#define CCOLS 50257
#define BLK   256

__device__ float g_rowL[NROWS];
__device__ unsigned int g_count = 0;   // self-resetting via atomicInc wrap

__device__ __forceinline__ float ex2f(float x) {
    float y;
    asm("ex2.approx.ftz.f32 %0, %1;" : "=f"(y) : "f"(x));
    return y;
}

#define SL2E (30.0f * 1.44269504088896340736f)   // S * log2(e)

__global__ __launch_bounds__(BLK) void amsm_kernel(
    const float* __restrict__ score,
    const int* __restrict__ labels,
    float* __restrict__ out)
{
    const int row = blockIdx.x;
    const int tid = threadIdx.x;
    const float* __restrict__ p = score + (size_t)row * CCOLS;

    // Row base is (row mod 4) floats off 16B alignment (50257 % 4 == 1).
    const int peel = (4 - (row & 3)) & 3;

    float s0 = 0.f, s1 = 0.f, s2 = 0.f, s3 = 0.f;
    if (tid < peel) s0 += ex2f(SL2E * p[tid]);

    const int n4 = (CCOLS - peel) >> 2;
    const float4* __restrict__ q = (const float4*)(p + peel);

    int i = tid;
    // 4 x LDG.128 in flight per thread
    for (; i + 3 * BLK < n4; i += 4 * BLK) {
        float4 a = q[i];
        float4 b = q[i + BLK];
        float4 c = q[i + 2 * BLK];
        float4 d = q[i + 3 * BLK];
        s0 += ex2f(SL2E * a.x); s1 += ex2f(SL2E * a.y);
        s2 += ex2f(SL2E * a.z); s3 += ex2f(SL2E * a.w);
        s0 += ex2f(SL2E * b.x); s1 += ex2f(SL2E * b.y);
        s2 += ex2f(SL2E * b.z); s3 += ex2f(SL2E * b.w);
        s0 += ex2f(SL2E * c.x); s1 += ex2f(SL2E * c.y);
        s2 += ex2f(SL2E * c.z); s3 += ex2f(SL2E * c.w);
        s0 += ex2f(SL2E * d.x); s1 += ex2f(SL2E * d.y);
        s2 += ex2f(SL2E * d.z); s3 += ex2f(SL2E * d.w);
    }
    for (; i < n4; i += BLK) {
        float4 a = q[i];
        s0 += ex2f(SL2E * a.x); s1 += ex2f(SL2E * a.y);
        s2 += ex2f(SL2E * a.z); s3 += ex2f(SL2E * a.w);
    }
    const int tail = peel + 4 * n4;
    if (tid < CCOLS - tail) s0 += ex2f(SL2E * p[tail + tid]);

    float sum = (s0 + s1) + (s2 + s3);

    // Block reduction
    __shared__ float red[BLK];
    red[tid] = sum;
    __syncthreads();
    #pragma unroll
    for (int off = BLK / 2; off >= 32; off >>= 1) {
        if (tid < off) red[tid] += red[tid + off];
        __syncthreads();
    }

    __shared__ unsigned s_last;
    if (tid < 32) {
        float v = red[tid];
        #pragma unroll
        for (int off = 16; off > 0; off >>= 1)
            v += __shfl_down_sync(0xFFFFFFFFu, v, off);
        if (tid == 0) {
            int lab = labels[row] & 1;             // 0 or 1
            float m = lab ? 0.4f : 0.1f;
            float t = p[lab];                      // target logit
            float num = 30.0f * (t - m);
            float excl = v - ex2f(SL2E * t);       // sum minus target term
            float denom = ex2f(num * 1.44269504088896340736f) + excl;
            g_rowL[row] = num - logf(denom);
            __threadfence();
            unsigned old = atomicInc(&g_count, NROWS - 1);  // wraps -> reset
            s_last = (old == NROWS - 1) ? 1u : 0u;
        }
    }
    __syncthreads();

    // Last-arriving block reduces all row losses and writes the output.
    if (s_last) {
        volatile float* rl = g_rowL;
        double acc = 0.0;
        for (int r = tid; r < NROWS; r += BLK)
            acc += (double)rl[r];
        __shared__ double dred[BLK];
        dred[tid] = acc;
        __syncthreads();
        #pragma unroll
        for (int off = BLK / 2; off > 0; off >>= 1) {
            if (tid < off) dred[tid] += dred[tid + off];
            __syncthreads();
        }
        if (tid == 0)
            out[0] = (float)(-dred[0] / (double)NROWS);
    }
}

extern "C" void kernel_launch(void* const* d_in, const int* in_sizes, int n_in,
                              void* d_out, int out_size)
{
    const float* score = (const float*)d_in[0];
    const int* labels = (const int*)d_in[1];
    float* out = (float*)d_out;

    amsm_kernel<<<NROWS, BLK>>>(score, labels, out);
}